// round 4
// baseline (speedup 1.0000x reference)
#include <cuda_runtime.h>
#include <math.h>

#define NROWS 6144
#define KDIM  128
#define NCLS  200
#define RPB   8
#define NBLK  (NROWS / RPB)      // 768
#define NTHR  512
#define NWARP (NTHR / 32)        // 16
#define SIMCAP 128
#define QBLKS 192

// GEMM tiling
#define GTM 64
#define GTN 512
#define GTHR 512
#define GSMEM (KDIM * GTM * 8)   // 65536

// ---- stats kernel shared memory layout (byte offsets) ----
#define SM_ROWS   0                                   // [8][6144] f32  = 196608
#define SM_SLAB   (SM_ROWS + RPB*NROWS*4)             // 6144 bytes
#define SM_HIST   (SM_SLAB + NROWS)                   // [8][256] int
#define SM_SIMV   (SM_HIST + RPB*256*4)               // [8][128] f32
#define SM_SCNT   (SM_SIMV + RPB*SIMCAP*4)            // [8] int
#define SM_MISC   (SM_SCNT + RPB*4)
#define MISC_SUMS  (SM_MISC + 0)
#define MISC_SUMD  (SM_MISC + 32)
#define MISC_SGT   (SM_MISC + 64)
#define MISC_SMIN  (SM_MISC + 96)
#define MISC_BP    (SM_MISC + 128)
#define MISC_BPD   (SM_MISC + 160)
#define MISC_NSIM  (SM_MISC + 192)
#define MISC_KSEL  (SM_MISC + 224)
#define MISC_KK    (SM_MISC + 256)
#define MISC_PFX   (SM_MISC + 288)
#define MISC_CGT   (SM_MISC + 320)
#define MISC_EP    (SM_MISC + 352)
#define MISC_EN    (SM_MISC + 384)
#define MISC_LP    (SM_MISC + 416)
#define MISC_LN    (SM_MISC + 448)
#define SM_WSCR   (SM_MISC + 512)                     // [16][8]
#define SMEM_BYTES (SM_WSCR + NWARP*8*4)

static __device__ float g_uhT[KDIM * NROWS];            // transposed tanh(u): [k][j]
static __device__ float g_inner[(size_t)NROWS * NROWS]; // full inner-product matrix
static __device__ int   g_label[NROWS];
static __device__ float g_rowpos[NROWS];
static __device__ float g_rowneg[NROWS];
static __device__ int   g_valid[NROWS];
static __device__ float g_qpart[QBLKS];

__device__ __forceinline__ unsigned f2key(float f) {
    unsigned u = __float_as_uint(f);
    return (u & 0x80000000u) ? ~u : (u | 0x80000000u);
}
__device__ __forceinline__ float key2f(unsigned k) {
    unsigned u = (k & 0x80000000u) ? (k ^ 0x80000000u) : ~k;
    return __uint_as_float(u);
}
__device__ __forceinline__ float clip64(float x) { return fminf(fmaxf(x, 0.f), 64.f); }
__device__ __forceinline__ float softplus_f(float x) {
    return fmaxf(x, 0.f) + __logf(1.f + __expf(-fabsf(x)));
}
__device__ __forceinline__ unsigned long long packww(float w) {
    unsigned long long r;
    asm("mov.b64 %0, {%1, %1};" : "=l"(r) : "f"(w));
    return r;
}
// warp-aggregated shared-memory histogram increment (bins cluster heavily)
__device__ __forceinline__ void aggHistAdd(int* hist, int idx) {
    unsigned active = __activemask();
    unsigned mask = __match_any_sync(active, idx);
    int leader = __ffs(mask) - 1;
    if ((int)(threadIdx.x & 31) == leader)
        atomicAdd(hist + idx, __popc(mask));
}

// deterministic 8-value block reductions (fixed order)
__device__ __forceinline__ void blockSum8F(float v[8], float* wscr, float* out8, int tid) {
    int lane = tid & 31, wid = tid >> 5;
    #pragma unroll
    for (int r = 0; r < 8; r++) {
        #pragma unroll
        for (int o = 16; o > 0; o >>= 1) v[r] += __shfl_xor_sync(0xFFFFFFFFu, v[r], o);
    }
    if (lane == 0) {
        #pragma unroll
        for (int r = 0; r < 8; r++) wscr[wid * 8 + r] = v[r];
    }
    __syncthreads();
    if (tid < 8) {
        float s = 0.f;
        #pragma unroll
        for (int w = 0; w < NWARP; w++) s += wscr[w * 8 + tid];
        out8[tid] = s;
    }
    __syncthreads();
}
__device__ __forceinline__ void blockSum8I(int v[8], int* wscr, int* out8, int tid) {
    int lane = tid & 31, wid = tid >> 5;
    #pragma unroll
    for (int r = 0; r < 8; r++) {
        #pragma unroll
        for (int o = 16; o > 0; o >>= 1) v[r] += __shfl_xor_sync(0xFFFFFFFFu, v[r], o);
    }
    if (lane == 0) {
        #pragma unroll
        for (int r = 0; r < 8; r++) wscr[wid * 8 + r] = v[r];
    }
    __syncthreads();
    if (tid < 8) {
        int s = 0;
        #pragma unroll
        for (int w = 0; w < NWARP; w++) s += wscr[w * 8 + tid];
        out8[tid] = s;
    }
    __syncthreads();
}

// ---------------- kernel 0: tanh + quantization partials + transpose ----------
__global__ void __launch_bounds__(256) tanh_kernel(const float* __restrict__ u) {
    __shared__ float tile[32][129];
    __shared__ float scr[8];
    const int tid = threadIdx.x;
    const int i0 = blockIdx.x * 32;
    float q = 0.f;
    for (int idx = tid; idx < 32 * KDIM; idx += 256) {
        int r = idx >> 7, k = idx & 127;
        float x = tanhf(u[(i0 + r) * KDIM + k]);
        tile[r][k] = x;
        float s = (x > 0.f) ? 1.f : ((x < 0.f) ? -1.f : 0.f);
        float d = x - s;
        q += d * d;
    }
    __syncthreads();
    for (int idx = tid; idx < 32 * KDIM; idx += 256) {
        int k = idx >> 5, i = idx & 31;
        g_uhT[k * NROWS + i0 + i] = tile[i][k];
    }
    #pragma unroll
    for (int o = 16; o > 0; o >>= 1) q += __shfl_xor_sync(0xFFFFFFFFu, q, o);
    if ((tid & 31) == 0) scr[tid >> 5] = q;
    __syncthreads();
    if (tid == 0) {
        float s = 0.f;
        for (int w = 0; w < 8; w++) s += scr[w];
        g_qpart[blockIdx.x] = s;
    }
}

// ---------------- kernel 1: one-hot -> label ---------------------------------
__global__ void label_kernel(const int* __restrict__ y) {
    int i = blockIdx.x * blockDim.x + threadIdx.x;
    if (i < NROWS) {
        int lab = 0;
        const int* yr = y + (size_t)i * NCLS;
        for (int c = 0; c < NCLS; c++) {
            if (yr[c] != 0) { lab = c; break; }
        }
        g_label[i] = lab;
    }
}

// ---------------- kernel 2: GEMM inner = uh @ uh^T  --------------------------
// tile [GTM=64 i x GTN=512 j], 512 threads, per-thread 8i x 8j register tile.
__global__ void __launch_bounds__(GTHR, 1) gemm_kernel() {
    extern __shared__ unsigned long long apk[];   // [KDIM][GTM] (a,a)-packed, 64 KB
    const int tid = threadIdx.x;
    const int i0 = blockIdx.x * GTM;
    const int j0 = blockIdx.y * GTN;

    for (int t = tid; t < KDIM * GTM; t += GTHR) {
        int k = t >> 6, i = t & 63;
        apk[k * GTM + i] = packww(g_uhT[(size_t)k * NROWS + i0 + i]);
    }
    __syncthreads();

    const int tjj = (tid & 63) * 8;       // j offset within tile
    const int tii = (tid >> 6) * 8;       // i offset within tile
    const float* Bp = g_uhT + (size_t)j0 + tjj;

    unsigned long long acc[8][4];
    #pragma unroll
    for (int i = 0; i < 8; i++)
        #pragma unroll
        for (int c = 0; c < 4; c++) acc[i][c] = 0ull;

    #pragma unroll 4
    for (int k = 0; k < KDIM; k++) {
        ulonglong2 b01 = *(const ulonglong2*)(Bp + (size_t)k * NROWS);
        ulonglong2 b23 = *(const ulonglong2*)(Bp + (size_t)k * NROWS + 4);
        #pragma unroll
        for (int i = 0; i < 8; i++) {
            unsigned long long a = apk[k * GTM + tii + i];
            asm("fma.rn.f32x2 %0, %1, %2, %0;" : "+l"(acc[i][0]) : "l"(b01.x), "l"(a));
            asm("fma.rn.f32x2 %0, %1, %2, %0;" : "+l"(acc[i][1]) : "l"(b01.y), "l"(a));
            asm("fma.rn.f32x2 %0, %1, %2, %0;" : "+l"(acc[i][2]) : "l"(b23.x), "l"(a));
            asm("fma.rn.f32x2 %0, %1, %2, %0;" : "+l"(acc[i][3]) : "l"(b23.y), "l"(a));
        }
    }

    #pragma unroll
    for (int i = 0; i < 8; i++) {
        size_t base = (size_t)(i0 + tii + i) * NROWS + j0 + tjj;
        ulonglong2 o1; o1.x = acc[i][0]; o1.y = acc[i][1];
        ulonglong2 o2; o2.x = acc[i][2]; o2.y = acc[i][3];
        *(ulonglong2*)(g_inner + base) = o1;
        *(ulonglong2*)(g_inner + base + 4) = o2;
    }
}

// ---------------- kernel 3: stats + loss over 8-row slabs --------------------
__global__ void __launch_bounds__(NTHR, 1) stats_loss_kernel() {
    extern __shared__ unsigned char sm[];
    float* rows               = (float*)(sm + SM_ROWS);
    unsigned char* slab       = (unsigned char*)(sm + SM_SLAB);
    int*   hist               = (int*)(sm + SM_HIST);
    float* simv               = (float*)(sm + SM_SIMV);
    int*   scnt               = (int*)(sm + SM_SCNT);
    float* sumS8              = (float*)(sm + MISC_SUMS);
    float* sumD8              = (float*)(sm + MISC_SUMD);
    float* sgt8               = (float*)(sm + MISC_SGT);
    float* sMin8              = (float*)(sm + MISC_SMIN);
    float* BP8                = (float*)(sm + MISC_BP);
    float* BPd8               = (float*)(sm + MISC_BPD);
    int*   nsim8              = (int*)(sm + MISC_NSIM);
    int*   ksel8              = (int*)(sm + MISC_KSEL);
    int*   kk8                = (int*)(sm + MISC_KK);
    unsigned* pfx8            = (unsigned*)(sm + MISC_PFX);
    int*   cgt8               = (int*)(sm + MISC_CGT);
    int*   ep8                = (int*)(sm + MISC_EP);
    int*   en8                = (int*)(sm + MISC_EN);
    float* lp8                = (float*)(sm + MISC_LP);
    float* ln8                = (float*)(sm + MISC_LN);
    float* wscrF              = (float*)(sm + SM_WSCR);
    int*   wscrI              = (int*)(sm + SM_WSCR);

    const int tid = threadIdx.x;
    const int i0  = blockIdx.x * RPB;

    // ---- load 8-row slab (contiguous 192 KB) + labels + zero hist ----
    {
        const float4* src = (const float4*)(g_inner + (size_t)i0 * NROWS);
        float4* dst = (float4*)rows;
        for (int t = tid; t < RPB * NROWS / 4; t += NTHR) dst[t] = src[t];
    }
    for (int t = tid; t < NROWS; t += NTHR) slab[t] = (unsigned char)g_label[t];
    for (int t = tid; t < RPB * 256; t += NTHR) hist[t] = 0;
    if (tid < RPB) scnt[tid] = 0;
    __syncthreads();

    unsigned long long labi64 = 0;
    #pragma unroll
    for (int r = 0; r < RPB; r++)
        labi64 |= ((unsigned long long)slab[i0 + r]) << (8 * r);

    // ---- S1: sums, similar collection, radix pass-0 histogram ----
    {
        float sS[8], sD[8];
        #pragma unroll
        for (int r = 0; r < 8; r++) { sS[r] = 0.f; sD[r] = 0.f; }
        for (int j = tid; j < NROWS; j += NTHR) {
            unsigned lab = slab[j];
            #pragma unroll
            for (int r = 0; r < RPB; r++) {
                float v = rows[r * NROWS + j];
                bool sim = ((unsigned)(labi64 >> (8 * r)) & 255u) == lab;
                if (sim) {
                    sS[r] += v;
                    int p = atomicAdd(&scnt[r], 1);
                    if (p < SIMCAP) simv[r * SIMCAP + p] = v;
                } else {
                    sD[r] += v;
                    aggHistAdd(hist, r * 256 + (int)(f2key(v) >> 24));
                }
            }
        }
        blockSum8F(sS, wscrF, sumS8, tid);
        blockSum8F(sD, wscrF, sumD8, tid);
    }
    __syncthreads();

    // ---- sMin + radix init (8-way parallel) ----
    if (tid < RPB) {
        int r = tid;
        int ns = scnt[r];
        nsim8[r] = ns;
        int nd = NROWS - ns;
        int ks = nd - (nd * 9) / 10;
        if (ks < 1) ks = 1;
        ksel8[r] = ks;
        kk8[r]   = ks;
        pfx8[r]  = 0u;
        int cnt = ns < SIMCAP ? ns : SIMCAP;
        int m = ns - (ns * 9) / 10;
        if (m < 1) m = 1;
        float* sv = simv + r * SIMCAP;
        float ssum = 0.f;
        for (int it = 0; it < m && it < cnt; it++) {
            int bi = it; float bv = sv[it];
            for (int t2 = it + 1; t2 < cnt; t2++) {
                float x = sv[t2];
                if (x < bv) { bv = x; bi = t2; }
            }
            sv[bi] = sv[it]; sv[it] = bv;
            ssum += bv;
        }
        sMin8[r] = clip64(ssum / (float)(m > 1 ? m : 1));
    }
    __syncthreads();

    // ---- radix select: 4 passes of 8 bits ----
    const int lane = tid & 31, wid = tid >> 5;
    #pragma unroll
    for (int p = 0; p < 4; p++) {
        if (p > 0) {
            int shift = 24 - 8 * p;
            for (int t = tid; t < RPB * 256; t += NTHR) hist[t] = 0;
            __syncthreads();
            for (int j = tid; j < NROWS; j += NTHR) {
                unsigned lab = slab[j];
                #pragma unroll
                for (int r = 0; r < RPB; r++) {
                    if ((((unsigned)(labi64 >> (8 * r)) & 255u) != lab)) {
                        unsigned key = f2key(rows[r * NROWS + j]);
                        if ((key >> (shift + 8)) == pfx8[r])
                            aggHistAdd(hist, r * 256 + (int)((key >> shift) & 255u));
                    }
                }
            }
            __syncthreads();
        }
        if (wid < RPB) {
            int r = wid;
            int kk = kk8[r];
            int csum = 0;
            int topbin = 255 - lane * 8;
            #pragma unroll
            for (int b = 0; b < 8; b++) csum += hist[r * 256 + topbin - b];
            int incl = csum;
            #pragma unroll
            for (int o = 1; o < 32; o <<= 1) {
                int t = __shfl_up_sync(0xFFFFFFFFu, incl, o);
                if (lane >= o) incl += t;
            }
            int excl = incl - csum;
            if (excl < kk && kk <= incl) {
                int running = excl;
                int bfound = 0, kknext = 0;
                #pragma unroll
                for (int b = 0; b < 8; b++) {
                    int bin = topbin - b;
                    int c = hist[r * 256 + bin];
                    running += c;
                    if (running >= kk) { bfound = bin; kknext = kk - (running - c); break; }
                }
                pfx8[r] = (pfx8[r] << 8) | (unsigned)bfound;
                kk8[r]  = kknext;
            }
        }
        __syncthreads();
    }

    // ---- S5: sum/count of dissimilar strictly above threshold ----
    {
        unsigned pf[8];
        #pragma unroll
        for (int r = 0; r < 8; r++) pf[r] = pfx8[r];
        float sg[8]; int cg[8];
        #pragma unroll
        for (int r = 0; r < 8; r++) { sg[r] = 0.f; cg[r] = 0; }
        for (int j = tid; j < NROWS; j += NTHR) {
            unsigned lab = slab[j];
            #pragma unroll
            for (int r = 0; r < RPB; r++) {
                if ((((unsigned)(labi64 >> (8 * r)) & 255u) != lab)) {
                    float v = rows[r * NROWS + j];
                    if (f2key(v) > pf[r]) { sg[r] += v; cg[r]++; }
                }
            }
        }
        blockSum8F(sg, wscrF, sgt8, tid);
        blockSum8I(cg, wscrI, cgt8, tid);
    }

    // ---- thresholds BP/BPd ----
    if (tid < RPB) {
        int r = tid;
        int ns = nsim8[r], nd = NROWS - ns;
        int ks = ksel8[r];
        float tval = key2f(pfx8[r]);
        float dsum = sgt8[r] + (float)(ks - cgt8[r]) * tval;
        float dMax = clip64(dsum / (float)(ks > 1 ? ks : 1));
        float meanS  = clip64(sumS8[r] / fmaxf((float)ns, 1.f));
        float meanDS = clip64(sumD8[r] / fmaxf((float)nd, 1.f));
        float sMin = sMin8[r];
        BP8[r]  = meanS  - (64.f - meanS) / 64.f * fabsf(meanS - dMax);
        BPd8[r] = meanDS + meanDS / 64.f * fabsf(meanDS - sMin);
    }
    __syncthreads();

    // ---- S6: loss sweep ----
    {
        const float C1 = -0.2871949906334119f;  // C_COEF = -ln(99)/16
        const float C2 = 2.f * C1;              // A_COEF * C_COEF (a == 2 exactly)
        float bp[8], bpd[8];
        #pragma unroll
        for (int r = 0; r < 8; r++) { bp[r] = BP8[r]; bpd[r] = BPd8[r]; }
        float lp[8], ln_[8]; int ep[8], en[8];
        #pragma unroll
        for (int r = 0; r < 8; r++) { lp[r] = 0.f; ln_[r] = 0.f; ep[r] = 0; en[r] = 0; }
        for (int j = tid; j < NROWS; j += NTHR) {
            unsigned lab = slab[j];
            #pragma unroll
            for (int r = 0; r < RPB; r++) {
                float v = rows[r * NROWS + j];
                bool sim = ((unsigned)(labi64 >> (8 * r)) & 255u) == lab;
                if (sim) {
                    if (v == bp[r]) ep[r]++;
                    else {
                        float dc = v - bp[r];
                        float f = (v > bp[r]) ? C1 * dc : C2 * dc;
                        lp[r] += softplus_f(f);
                    }
                } else {
                    if (v == bpd[r]) en[r]++;
                    else {
                        float dc = v - bpd[r];
                        float f = (v < bpd[r]) ? C1 * dc : C2 * dc;
                        ln_[r] += softplus_f(-f);
                    }
                }
            }
        }
        blockSum8F(lp, wscrF, lp8, tid);
        blockSum8F(ln_, wscrF, ln8, tid);
        blockSum8I(ep, wscrI, ep8, tid);
        blockSum8I(en, wscrI, en8, tid);
    }

    if (tid < RPB) {
        int r = tid;
        int ns = nsim8[r], nd = NROWS - ns;
        int cp = ns - ep8[r];
        int cn = nd - en8[r];
        g_rowpos[i0 + r] = lp8[r] / fmaxf((float)cp, 1.f);
        g_rowneg[i0 + r] = ln8[r] / fmaxf((float)cn, 1.f);
        g_valid[i0 + r]  = (ns > 0 && nd > 0) ? 1 : 0;
    }
}

// ---------------- kernel 4: final scalar -------------------------------------
__global__ void __launch_bounds__(256) final_kernel(float* __restrict__ out) {
    __shared__ float scrF[8];
    __shared__ int scrI[8];
    int tid = threadIdx.x;
    float ps = 0.f, ns = 0.f; int cv = 0;
    for (int i = tid; i < NROWS; i += 256) {
        if (g_valid[i]) { ps += g_rowpos[i]; ns += g_rowneg[i]; cv++; }
    }
    float q = 0.f;
    for (int i = tid; i < QBLKS; i += 256) q += g_qpart[i];
    #pragma unroll
    for (int o = 16; o > 0; o >>= 1) {
        ps += __shfl_xor_sync(0xFFFFFFFFu, ps, o);
        ns += __shfl_xor_sync(0xFFFFFFFFu, ns, o);
        cv += __shfl_xor_sync(0xFFFFFFFFu, cv, o);
        q  += __shfl_xor_sync(0xFFFFFFFFu, q, o);
    }
    if ((tid & 31) == 0) { scrF[tid >> 5] = ps; scrI[tid >> 5] = cv; }
    __syncthreads();
    __shared__ float scrF2[8]; __shared__ float scrF3[8];
    if ((tid & 31) == 0) { scrF2[tid >> 5] = ns; scrF3[tid >> 5] = q; }
    __syncthreads();
    if (tid == 0) {
        float psum = 0.f, nsum = 0.f, qs = 0.f; int cnt = 0;
        for (int w = 0; w < 8; w++) {
            psum += scrF[w]; nsum += scrF2[w]; qs += scrF3[w]; cnt += scrI[w];
        }
        float posL = (cnt > 0) ? psum / fmaxf((float)cnt, 1.f) : 0.f;
        float navL = (cnt > 0) ? nsum / fmaxf((float)cnt, 1.f) : 0.f;
        float ql = 0.1f * qs / (float)(NROWS * KDIM);
        out[0] = posL + navL + ql;
    }
}

extern "C" void kernel_launch(void* const* d_in, const int* in_sizes, int n_in,
                              void* d_out, int out_size) {
    const float* u = (const float*)d_in[0];
    const int*   y = (const int*)d_in[1];
    (void)in_sizes; (void)n_in; (void)out_size;

    cudaFuncSetAttribute(gemm_kernel,
                         cudaFuncAttributeMaxDynamicSharedMemorySize, GSMEM);
    cudaFuncSetAttribute(stats_loss_kernel,
                         cudaFuncAttributeMaxDynamicSharedMemorySize, SMEM_BYTES);

    tanh_kernel<<<QBLKS, 256>>>(u);
    label_kernel<<<(NROWS + 255) / 256, 256>>>(y);
    dim3 ggrid(NROWS / GTM, NROWS / GTN);     // (96, 12)
    gemm_kernel<<<ggrid, GTHR, GSMEM>>>();
    stats_loss_kernel<<<NBLK, NTHR, SMEM_BYTES>>>();
    final_kernel<<<1, 256>>>((float*)d_out);
}

// round 5
// speedup vs baseline: 1.2780x; 1.2780x over previous
#include <cuda_runtime.h>
#include <math.h>

#define NROWS 6144
#define KDIM  128
#define NCLS  200
#define RPB   8
#define NBLK  (NROWS / RPB)      // 768
#define NTHR  1024
#define NWARP (NTHR / 32)        // 32
#define SIMCAP 128
#define QBLKS 192

// GEMM tiling
#define GTM 64
#define GTN 512
#define GTHR 512
#define GSMEM (KDIM * GTM * 8)   // 65536

// ---- stats kernel shared memory layout (byte offsets) ----
#define SM_ROWS   0                                   // [8][6144] f32 = 196608
#define SM_SLAB   196608                              // 6144
#define SM_SIMM   202752                              // 6144
#define SM_HIST   208896                              // [8][256] int = 8192
#define SM_VHIST  217088                              // [8][256] f32 = 8192
#define SM_SIMV   225280                              // [8][128] f32 = 4096
#define SM_SCNT   229376                              // 32
#define SM_MISC   229408                              // 512
#define SM_WSCR   229920                              // 1024
#define SMEM_BYTES 230944

#define MISC_SUMS  (SM_MISC + 0)
#define MISC_SUMD  (SM_MISC + 32)
#define MISC_SGT   (SM_MISC + 64)
#define MISC_VSUF  (SM_MISC + 96)
#define MISC_SMIN  (SM_MISC + 128)
#define MISC_BP    (SM_MISC + 160)
#define MISC_BPD   (SM_MISC + 192)
#define MISC_LP    (SM_MISC + 224)
#define MISC_LN    (SM_MISC + 256)
#define MISC_NSIM  (SM_MISC + 288)
#define MISC_KSEL  (SM_MISC + 320)
#define MISC_KK    (SM_MISC + 352)
#define MISC_PFX   (SM_MISC + 384)
#define MISC_CGT   (SM_MISC + 416)
#define MISC_EP    (SM_MISC + 448)
#define MISC_EN    (SM_MISC + 480)

static __device__ float g_uhT[KDIM * NROWS];            // transposed tanh(u): [k][j]
static __device__ float g_inner[(size_t)NROWS * NROWS]; // full inner-product matrix
static __device__ int   g_label[NROWS];
static __device__ float g_rowpos[NROWS];
static __device__ float g_rowneg[NROWS];
static __device__ int   g_valid[NROWS];
static __device__ float g_qpart[QBLKS];

__device__ __forceinline__ unsigned f2key(float f) {
    unsigned u = __float_as_uint(f);
    return u ^ ((unsigned)(((int)u) >> 31) | 0x80000000u);
}
__device__ __forceinline__ float key2f(unsigned k) {
    unsigned u = (k & 0x80000000u) ? (k ^ 0x80000000u) : ~k;
    return __uint_as_float(u);
}
__device__ __forceinline__ float clip64(float x) { return fminf(fmaxf(x, 0.f), 64.f); }
__device__ __forceinline__ float softplus_f(float x) {
    return fmaxf(x, 0.f) + __logf(1.f + __expf(-fabsf(x)));
}
__device__ __forceinline__ unsigned long long packww(float w) {
    unsigned long long r;
    asm("mov.b64 %0, {%1, %1};" : "=l"(r) : "f"(w));
    return r;
}
// warp-aggregated shared-memory histogram increment (bins cluster heavily)
__device__ __forceinline__ void aggHistAdd(int* hist, int idx) {
    unsigned active = __activemask();
    unsigned mask = __match_any_sync(active, idx);
    int leader = __ffs(mask) - 1;
    if ((int)(threadIdx.x & 31) == leader)
        atomicAdd(hist + idx, __popc(mask));
}

// deterministic 8-value block reductions (fixed order)
__device__ __forceinline__ void blockSum8F(float v[8], float* wscr, float* out8, int tid) {
    int lane = tid & 31, wid = tid >> 5;
    #pragma unroll
    for (int r = 0; r < 8; r++) {
        #pragma unroll
        for (int o = 16; o > 0; o >>= 1) v[r] += __shfl_xor_sync(0xFFFFFFFFu, v[r], o);
    }
    if (lane == 0) {
        #pragma unroll
        for (int r = 0; r < 8; r++) wscr[wid * 8 + r] = v[r];
    }
    __syncthreads();
    if (tid < 8) {
        float s = 0.f;
        #pragma unroll
        for (int w = 0; w < NWARP; w++) s += wscr[w * 8 + tid];
        out8[tid] = s;
    }
    __syncthreads();
}
__device__ __forceinline__ void blockSum8I(int v[8], int* wscr, int* out8, int tid) {
    int lane = tid & 31, wid = tid >> 5;
    #pragma unroll
    for (int r = 0; r < 8; r++) {
        #pragma unroll
        for (int o = 16; o > 0; o >>= 1) v[r] += __shfl_xor_sync(0xFFFFFFFFu, v[r], o);
    }
    if (lane == 0) {
        #pragma unroll
        for (int r = 0; r < 8; r++) wscr[wid * 8 + r] = v[r];
    }
    __syncthreads();
    if (tid < 8) {
        int s = 0;
        #pragma unroll
        for (int w = 0; w < NWARP; w++) s += wscr[w * 8 + tid];
        out8[tid] = s;
    }
    __syncthreads();
}

// warp-cooperative reverse scan over one 256-bin histogram row.
// All 32 lanes get the chosen bin and the residual k. (Bins scanned high->low.)
__device__ __forceinline__ int radixPick(const int* histrow, int kk, int lane,
                                         int* kknext_out) {
    int topbin = 255 - lane * 8;
    int csum = 0;
    #pragma unroll
    for (int b = 0; b < 8; b++) csum += histrow[topbin - b];
    int incl = csum;
    #pragma unroll
    for (int o = 1; o < 32; o <<= 1) {
        int t = __shfl_up_sync(0xFFFFFFFFu, incl, o);
        if (lane >= o) incl += t;
    }
    int excl = incl - csum;
    int hit = (excl < kk && kk <= incl) ? 1 : 0;
    unsigned who = __ballot_sync(0xFFFFFFFFu, hit);
    int src = __ffs(who) - 1;
    int bfound = 0, kknext = 0;
    if (hit) {
        int running = excl;
        #pragma unroll
        for (int b = 0; b < 8; b++) {
            int bin = topbin - b;
            int c = histrow[bin];
            running += c;
            if (running >= kk) { bfound = bin; kknext = kk - (running - c); break; }
        }
    }
    bfound = __shfl_sync(0xFFFFFFFFu, bfound, src);
    kknext = __shfl_sync(0xFFFFFFFFu, kknext, src);
    *kknext_out = kknext;
    return bfound;
}

// ---------------- kernel 0: tanh + quantization partials + transpose ----------
__global__ void __launch_bounds__(256) tanh_kernel(const float* __restrict__ u) {
    __shared__ float tile[32][129];
    __shared__ float scr[8];
    const int tid = threadIdx.x;
    const int i0 = blockIdx.x * 32;
    float q = 0.f;
    for (int idx = tid; idx < 32 * KDIM; idx += 256) {
        int r = idx >> 7, k = idx & 127;
        float x = tanhf(u[(i0 + r) * KDIM + k]);
        tile[r][k] = x;
        float s = (x > 0.f) ? 1.f : ((x < 0.f) ? -1.f : 0.f);
        float d = x - s;
        q += d * d;
    }
    __syncthreads();
    for (int idx = tid; idx < 32 * KDIM; idx += 256) {
        int k = idx >> 5, i = idx & 31;
        g_uhT[k * NROWS + i0 + i] = tile[i][k];
    }
    #pragma unroll
    for (int o = 16; o > 0; o >>= 1) q += __shfl_xor_sync(0xFFFFFFFFu, q, o);
    if ((tid & 31) == 0) scr[tid >> 5] = q;
    __syncthreads();
    if (tid == 0) {
        float s = 0.f;
        for (int w = 0; w < 8; w++) s += scr[w];
        g_qpart[blockIdx.x] = s;
    }
}

// ---------------- kernel 1: one-hot -> label ---------------------------------
__global__ void label_kernel(const int* __restrict__ y) {
    int i = blockIdx.x * blockDim.x + threadIdx.x;
    if (i < NROWS) {
        int lab = 0;
        const int* yr = y + (size_t)i * NCLS;
        for (int c = 0; c < NCLS; c++) {
            if (yr[c] != 0) { lab = c; break; }
        }
        g_label[i] = lab;
    }
}

// ---------------- kernel 2: GEMM inner = uh @ uh^T  --------------------------
__global__ void __launch_bounds__(GTHR, 1) gemm_kernel() {
    extern __shared__ unsigned long long apk[];   // [KDIM][GTM] (a,a)-packed
    const int tid = threadIdx.x;
    const int i0 = blockIdx.x * GTM;
    const int j0 = blockIdx.y * GTN;

    for (int t = tid; t < KDIM * GTM; t += GTHR) {
        int k = t >> 6, i = t & 63;
        apk[k * GTM + i] = packww(g_uhT[(size_t)k * NROWS + i0 + i]);
    }
    __syncthreads();

    const int tjj = (tid & 63) * 8;
    const int tii = (tid >> 6) * 8;
    const float* Bp = g_uhT + (size_t)j0 + tjj;

    unsigned long long acc[8][4];
    #pragma unroll
    for (int i = 0; i < 8; i++)
        #pragma unroll
        for (int c = 0; c < 4; c++) acc[i][c] = 0ull;

    ulonglong2 b01 = *(const ulonglong2*)(Bp);
    ulonglong2 b23 = *(const ulonglong2*)(Bp + 4);
    #pragma unroll 2
    for (int k = 0; k < KDIM; k++) {
        ulonglong2 n01, n23;
        if (k + 1 < KDIM) {
            n01 = *(const ulonglong2*)(Bp + (size_t)(k + 1) * NROWS);
            n23 = *(const ulonglong2*)(Bp + (size_t)(k + 1) * NROWS + 4);
        }
        #pragma unroll
        for (int i = 0; i < 8; i++) {
            unsigned long long a = apk[k * GTM + tii + i];
            asm("fma.rn.f32x2 %0, %1, %2, %0;" : "+l"(acc[i][0]) : "l"(b01.x), "l"(a));
            asm("fma.rn.f32x2 %0, %1, %2, %0;" : "+l"(acc[i][1]) : "l"(b01.y), "l"(a));
            asm("fma.rn.f32x2 %0, %1, %2, %0;" : "+l"(acc[i][2]) : "l"(b23.x), "l"(a));
            asm("fma.rn.f32x2 %0, %1, %2, %0;" : "+l"(acc[i][3]) : "l"(b23.y), "l"(a));
        }
        b01 = n01; b23 = n23;
    }

    #pragma unroll
    for (int i = 0; i < 8; i++) {
        size_t base = (size_t)(i0 + tii + i) * NROWS + j0 + tjj;
        ulonglong2 o1; o1.x = acc[i][0]; o1.y = acc[i][1];
        ulonglong2 o2; o2.x = acc[i][2]; o2.y = acc[i][3];
        *(ulonglong2*)(g_inner + base) = o1;
        *(ulonglong2*)(g_inner + base + 4) = o2;
    }
}

// ---------------- kernel 3: stats + loss over 8-row slabs --------------------
__global__ void __launch_bounds__(NTHR, 1) stats_loss_kernel() {
    extern __shared__ unsigned char sm[];
    float* rows          = (float*)(sm + SM_ROWS);
    unsigned char* slab  = (unsigned char*)(sm + SM_SLAB);
    unsigned char* simm  = (unsigned char*)(sm + SM_SIMM);
    int*   hist          = (int*)(sm + SM_HIST);
    float* vhist         = (float*)(sm + SM_VHIST);
    float* simv          = (float*)(sm + SM_SIMV);
    int*   scnt          = (int*)(sm + SM_SCNT);
    float* sumS8         = (float*)(sm + MISC_SUMS);
    float* sumD8         = (float*)(sm + MISC_SUMD);
    float* sgt8          = (float*)(sm + MISC_SGT);
    float* vsuf8         = (float*)(sm + MISC_VSUF);
    float* sMin8         = (float*)(sm + MISC_SMIN);
    float* BP8           = (float*)(sm + MISC_BP);
    float* BPd8          = (float*)(sm + MISC_BPD);
    float* lp8           = (float*)(sm + MISC_LP);
    float* ln8           = (float*)(sm + MISC_LN);
    int*   nsim8         = (int*)(sm + MISC_NSIM);
    int*   ksel8         = (int*)(sm + MISC_KSEL);
    int*   kk8           = (int*)(sm + MISC_KK);
    unsigned* pfx8       = (unsigned*)(sm + MISC_PFX);
    int*   cgt8          = (int*)(sm + MISC_CGT);
    int*   ep8           = (int*)(sm + MISC_EP);
    int*   en8           = (int*)(sm + MISC_EN);
    float* wscrF         = (float*)(sm + SM_WSCR);
    int*   wscrI         = (int*)(sm + SM_WSCR);

    const int tid = threadIdx.x;
    const int lane = tid & 31, wid = tid >> 5;
    const int i0  = blockIdx.x * RPB;

    // ---- setup: slab of 8 rows, labels, zero hists ----
    {
        const float4* src = (const float4*)(g_inner + (size_t)i0 * NROWS);
        float4* dst = (float4*)rows;
        #pragma unroll 4
        for (int t = tid; t < RPB * NROWS / 4; t += NTHR) dst[t] = src[t];
    }
    for (int t = tid; t < NROWS; t += NTHR) slab[t] = (unsigned char)g_label[t];
    for (int t = tid; t < RPB * 256; t += NTHR) hist[t] = 0;
    if (tid < RPB) scnt[tid] = 0;
    __syncthreads();

    unsigned labr[8];
    #pragma unroll
    for (int r = 0; r < RPB; r++) labr[r] = slab[i0 + r];

    // ---- S1: sums, similarity mask, similar collection, radix pass-0 hist ----
    {
        float sS[8], sD[8];
        #pragma unroll
        for (int r = 0; r < 8; r++) { sS[r] = 0.f; sD[r] = 0.f; }
        for (int j = tid; j < NROWS; j += NTHR) {
            unsigned lab = slab[j];
            unsigned m = 0;
            #pragma unroll
            for (int r = 0; r < RPB; r++) m |= (lab == labr[r]) ? (1u << r) : 0u;
            simm[j] = (unsigned char)m;
            #pragma unroll
            for (int r = 0; r < RPB; r++) {
                float v = rows[r * NROWS + j];
                if ((m >> r) & 1u) {
                    sS[r] += v;
                    int p = atomicAdd(&scnt[r], 1);
                    if (p < SIMCAP) simv[r * SIMCAP + p] = v;
                } else {
                    sD[r] += v;
                    aggHistAdd(hist, r * 256 + (int)(f2key(v) >> 24));
                }
            }
        }
        blockSum8F(sS, wscrF, sumS8, tid);
        blockSum8F(sD, wscrF, sumD8, tid);
    }

    // ---- sMin + radix init (8-way parallel on threads 0..7) ----
    if (tid < RPB) {
        int r = tid;
        int ns = scnt[r];
        nsim8[r] = ns;
        int nd = NROWS - ns;
        int ks = nd - (nd * 9) / 10;
        if (ks < 1) ks = 1;
        ksel8[r] = ks;
        kk8[r]   = ks;
        int cnt = ns < SIMCAP ? ns : SIMCAP;
        int m = ns - (ns * 9) / 10;
        if (m < 1) m = 1;
        float* sv = simv + r * SIMCAP;
        float ssum = 0.f;
        for (int it = 0; it < m && it < cnt; it++) {
            int bi = it; float bv = sv[it];
            for (int t2 = it + 1; t2 < cnt; t2++) {
                float x = sv[t2];
                if (x < bv) { bv = x; bi = t2; }
            }
            sv[bi] = sv[it]; sv[it] = bv;
            ssum += bv;
        }
        sMin8[r] = clip64(ssum / (float)(m > 1 ? m : 1));
    }
    __syncthreads();

    // ---- radix pass-0 pick (warps 0..7) ----
    if (wid < RPB) {
        int kknext;
        int b0 = radixPick(hist + wid * 256, kk8[wid], lane, &kknext);
        if (lane == 0) { pfx8[wid] = (unsigned)b0; kk8[wid] = kknext; }
    }
    __syncthreads();

    // ---- P1 sweep: refine byte 1 ----
    for (int t = tid; t < RPB * 256; t += NTHR) hist[t] = 0;
    __syncthreads();
    {
        unsigned p0[8];
        #pragma unroll
        for (int r = 0; r < 8; r++) p0[r] = pfx8[r];
        for (int j = tid; j < NROWS; j += NTHR) {
            unsigned m = simm[j];
            #pragma unroll
            for (int r = 0; r < RPB; r++) {
                if (!((m >> r) & 1u)) {
                    unsigned key = f2key(rows[r * NROWS + j]);
                    if ((key >> 24) == p0[r])
                        atomicAdd(&hist[r * 256 + (int)((key >> 16) & 255u)], 1);
                }
            }
        }
    }
    __syncthreads();
    if (wid < RPB) {
        int kknext;
        int b1 = radixPick(hist + wid * 256, kk8[wid], lane, &kknext);
        if (lane == 0) {
            pfx8[wid] = (pfx8[wid] << 8) | (unsigned)b1;   // 16-bit prefix
            kk8[wid] = kknext;
        }
    }
    __syncthreads();

    // ---- P2 sweep: refine byte 2, plus sum/count above 16-bit prefix ----
    for (int t = tid; t < RPB * 256; t += NTHR) { hist[t] = 0; vhist[t] = 0.f; }
    __syncthreads();
    {
        unsigned p16[8];
        #pragma unroll
        for (int r = 0; r < 8; r++) p16[r] = pfx8[r];
        float sg[8]; int cg[8];
        #pragma unroll
        for (int r = 0; r < 8; r++) { sg[r] = 0.f; cg[r] = 0; }
        for (int j = tid; j < NROWS; j += NTHR) {
            unsigned m = simm[j];
            #pragma unroll
            for (int r = 0; r < RPB; r++) {
                if (!((m >> r) & 1u)) {
                    float v = rows[r * NROWS + j];
                    unsigned key = f2key(v);
                    unsigned hi = key >> 16;
                    if (hi > p16[r]) { sg[r] += v; cg[r]++; }
                    else if (hi == p16[r]) {
                        int bin = (int)((key >> 8) & 255u);
                        atomicAdd(&hist[r * 256 + bin], 1);
                        atomicAdd(&vhist[r * 256 + bin], v);
                    }
                }
            }
        }
        blockSum8F(sg, wscrF, sgt8, tid);
        blockSum8I(cg, wscrI, cgt8, tid);
    }
    if (wid < RPB) {
        int kknext;
        int b2 = radixPick(hist + wid * 256, kk8[wid], lane, &kknext);
        // suffix value-sum over bins > b2 (deterministic lane order)
        int topbin = 255 - lane * 8;
        float vp = 0.f;
        #pragma unroll
        for (int b = 0; b < 8; b++) {
            int bin = topbin - b;
            if (bin > b2) vp += vhist[wid * 256 + bin];
        }
        #pragma unroll
        for (int o = 16; o > 0; o >>= 1) vp += __shfl_xor_sync(0xFFFFFFFFu, vp, o);
        if (lane == 0) {
            pfx8[wid] = (pfx8[wid] << 8) | (unsigned)b2;   // 24-bit prefix
            kk8[wid] = kknext;                              // residual ties in bin b2
            vsuf8[wid] = vp;
        }
    }
    __syncthreads();

    // ---- thresholds BP/BPd ----
    if (tid < RPB) {
        int r = tid;
        int ns = nsim8[r], nd = NROWS - ns;
        int ks = ksel8[r];
        float tval = key2f((pfx8[r] << 8) | 0x80u);   // mid of 24-bit bin
        float dsum = sgt8[r] + vsuf8[r] + (float)kk8[r] * tval;
        float dMax = clip64(dsum / (float)(ks > 1 ? ks : 1));
        float meanS  = clip64(sumS8[r] / fmaxf((float)ns, 1.f));
        float meanDS = clip64(sumD8[r] / fmaxf((float)nd, 1.f));
        float sMin = sMin8[r];
        BP8[r]  = meanS  - (64.f - meanS) / 64.f * fabsf(meanS - dMax);
        BPd8[r] = meanDS + meanDS / 64.f * fabsf(meanDS - sMin);
    }
    __syncthreads();

    // ---- S6: loss sweep ----
    {
        const float C1 = -0.2871949906334119f;  // C_COEF = -ln(99)/16
        const float C2 = 2.f * C1;              // A_COEF * C_COEF (a == 2 exactly)
        float bp[8], bpd[8];
        #pragma unroll
        for (int r = 0; r < 8; r++) { bp[r] = BP8[r]; bpd[r] = BPd8[r]; }
        float lp[8], ln_[8]; int ep[8], en[8];
        #pragma unroll
        for (int r = 0; r < 8; r++) { lp[r] = 0.f; ln_[r] = 0.f; ep[r] = 0; en[r] = 0; }
        for (int j = tid; j < NROWS; j += NTHR) {
            unsigned m = simm[j];
            #pragma unroll
            for (int r = 0; r < RPB; r++) {
                float v = rows[r * NROWS + j];
                if ((m >> r) & 1u) {
                    if (v == bp[r]) ep[r]++;
                    else {
                        float dc = v - bp[r];
                        float f = (v > bp[r]) ? C1 * dc : C2 * dc;
                        lp[r] += softplus_f(f);
                    }
                } else {
                    if (v == bpd[r]) en[r]++;
                    else {
                        float dc = v - bpd[r];
                        float f = (v < bpd[r]) ? C1 * dc : C2 * dc;
                        ln_[r] += softplus_f(-f);
                    }
                }
            }
        }
        blockSum8F(lp, wscrF, lp8, tid);
        blockSum8F(ln_, wscrF, ln8, tid);
        blockSum8I(ep, wscrI, ep8, tid);
        blockSum8I(en, wscrI, en8, tid);
    }

    if (tid < RPB) {
        int r = tid;
        int ns = nsim8[r], nd = NROWS - ns;
        int cp = ns - ep8[r];
        int cn = nd - en8[r];
        g_rowpos[i0 + r] = lp8[r] / fmaxf((float)cp, 1.f);
        g_rowneg[i0 + r] = ln8[r] / fmaxf((float)cn, 1.f);
        g_valid[i0 + r]  = (ns > 0 && nd > 0) ? 1 : 0;
    }
}

// ---------------- kernel 4: final scalar -------------------------------------
__global__ void __launch_bounds__(256) final_kernel(float* __restrict__ out) {
    __shared__ float scrF[8];
    __shared__ int scrI[8];
    int tid = threadIdx.x;
    float ps = 0.f, ns = 0.f; int cv = 0;
    for (int i = tid; i < NROWS; i += 256) {
        if (g_valid[i]) { ps += g_rowpos[i]; ns += g_rowneg[i]; cv++; }
    }
    float q = 0.f;
    for (int i = tid; i < QBLKS; i += 256) q += g_qpart[i];
    #pragma unroll
    for (int o = 16; o > 0; o >>= 1) {
        ps += __shfl_xor_sync(0xFFFFFFFFu, ps, o);
        ns += __shfl_xor_sync(0xFFFFFFFFu, ns, o);
        cv += __shfl_xor_sync(0xFFFFFFFFu, cv, o);
        q  += __shfl_xor_sync(0xFFFFFFFFu, q, o);
    }
    if ((tid & 31) == 0) { scrF[tid >> 5] = ps; scrI[tid >> 5] = cv; }
    __syncthreads();
    __shared__ float scrF2[8]; __shared__ float scrF3[8];
    if ((tid & 31) == 0) { scrF2[tid >> 5] = ns; scrF3[tid >> 5] = q; }
    __syncthreads();
    if (tid == 0) {
        float psum = 0.f, nsum = 0.f, qs = 0.f; int cnt = 0;
        for (int w = 0; w < 8; w++) {
            psum += scrF[w]; nsum += scrF2[w]; qs += scrF3[w]; cnt += scrI[w];
        }
        float posL = (cnt > 0) ? psum / fmaxf((float)cnt, 1.f) : 0.f;
        float navL = (cnt > 0) ? nsum / fmaxf((float)cnt, 1.f) : 0.f;
        float ql = 0.1f * qs / (float)(NROWS * KDIM);
        out[0] = posL + navL + ql;
    }
}

extern "C" void kernel_launch(void* const* d_in, const int* in_sizes, int n_in,
                              void* d_out, int out_size) {
    const float* u = (const float*)d_in[0];
    const int*   y = (const int*)d_in[1];
    (void)in_sizes; (void)n_in; (void)out_size;

    cudaFuncSetAttribute(gemm_kernel,
                         cudaFuncAttributeMaxDynamicSharedMemorySize, GSMEM);
    cudaFuncSetAttribute(stats_loss_kernel,
                         cudaFuncAttributeMaxDynamicSharedMemorySize, SMEM_BYTES);

    tanh_kernel<<<QBLKS, 256>>>(u);
    label_kernel<<<(NROWS + 255) / 256, 256>>>(y);
    dim3 ggrid(NROWS / GTM, NROWS / GTN);     // (96, 12)
    gemm_kernel<<<ggrid, GTHR, GSMEM>>>();
    stats_loss_kernel<<<NBLK, NTHR, SMEM_BYTES>>>();
    final_kernel<<<1, 256>>>((float*)d_out);
}

// round 6
// speedup vs baseline: 1.4585x; 1.1412x over previous
#include <cuda_runtime.h>
#include <math.h>

#define NROWS 6144
#define KDIM  128
#define NCLS  200
#define RPB   8
#define NBLK  (NROWS / RPB)      // 768
#define NTHR  1024
#define NWARP (NTHR / 32)        // 32
#define SIMCAP 128
#define QBLKS 192

// GEMM tiling
#define GTM 64
#define GTN 512
#define GTHR 512
#define GSMEM (KDIM * GTM * 8)   // 65536

// ---- stats kernel shared memory layout (byte offsets) ----
#define SM_ROWS   0                                   // [8][6144] f32 = 196608
#define SM_SLAB   196608                              // 6144
#define SM_SIMM   202752                              // 6144
#define SM_HIST   208896                              // [8][256] int = 8192
#define SM_VHIST  217088                              // [8][256] f32 = 8192
#define SM_SIMV   225280                              // [8][128] f32 = 4096
#define SM_SCNT   229376                              // 32
#define SM_MISC   229408                              // 512
#define SM_WSCR   229920                              // 1024
#define SMEM_BYTES 230944

#define MISC_SUMS  (SM_MISC + 0)
#define MISC_SUMD  (SM_MISC + 32)
#define MISC_SGT   (SM_MISC + 64)
#define MISC_VSUF  (SM_MISC + 96)
#define MISC_SMIN  (SM_MISC + 128)
#define MISC_BP    (SM_MISC + 160)
#define MISC_BPD   (SM_MISC + 192)
#define MISC_LP    (SM_MISC + 224)
#define MISC_LN    (SM_MISC + 256)
#define MISC_NSIM  (SM_MISC + 288)
#define MISC_KSEL  (SM_MISC + 320)
#define MISC_KK    (SM_MISC + 352)
#define MISC_PFX   (SM_MISC + 384)
#define MISC_CGT   (SM_MISC + 416)
#define MISC_EP    (SM_MISC + 448)
#define MISC_EN    (SM_MISC + 480)

static __device__ float g_uhT[KDIM * NROWS];            // transposed tanh(u): [k][j]
static __device__ float g_inner[(size_t)NROWS * NROWS]; // full inner-product matrix
static __device__ int   g_label[NROWS];
static __device__ float g_rowpos[NROWS];
static __device__ float g_rowneg[NROWS];
static __device__ int   g_valid[NROWS];
static __device__ float g_qpart[QBLKS];

__device__ __forceinline__ unsigned f2key(float f) {
    unsigned u = __float_as_uint(f);
    return u ^ ((unsigned)(((int)u) >> 31) | 0x80000000u);
}
__device__ __forceinline__ float clip64(float x) { return fminf(fmaxf(x, 0.f), 64.f); }
__device__ __forceinline__ float softplus_f(float x) {
    return fmaxf(x, 0.f) + __logf(1.f + __expf(-fabsf(x)));
}
__device__ __forceinline__ unsigned long long packww(float w) {
    unsigned long long r;
    asm("mov.b64 %0, {%1, %1};" : "=l"(r) : "f"(w));
    return r;
}
// warp-aggregated shared-memory histogram increment (bins cluster heavily)
__device__ __forceinline__ void aggHistAdd(int* hist, int idx) {
    unsigned active = __activemask();
    unsigned mask = __match_any_sync(active, idx);
    int leader = __ffs(mask) - 1;
    if ((int)(threadIdx.x & 31) == leader)
        atomicAdd(hist + idx, __popc(mask));
}

// deterministic 8-value block reductions (fixed order)
__device__ __forceinline__ void blockSum8F(float v[8], float* wscr, float* out8, int tid) {
    int lane = tid & 31, wid = tid >> 5;
    #pragma unroll
    for (int r = 0; r < 8; r++) {
        #pragma unroll
        for (int o = 16; o > 0; o >>= 1) v[r] += __shfl_xor_sync(0xFFFFFFFFu, v[r], o);
    }
    if (lane == 0) {
        #pragma unroll
        for (int r = 0; r < 8; r++) wscr[wid * 8 + r] = v[r];
    }
    __syncthreads();
    if (tid < 8) {
        float s = 0.f;
        #pragma unroll
        for (int w = 0; w < NWARP; w++) s += wscr[w * 8 + tid];
        out8[tid] = s;
    }
    __syncthreads();
}
__device__ __forceinline__ void blockSum8I(int v[8], int* wscr, int* out8, int tid) {
    int lane = tid & 31, wid = tid >> 5;
    #pragma unroll
    for (int r = 0; r < 8; r++) {
        #pragma unroll
        for (int o = 16; o > 0; o >>= 1) v[r] += __shfl_xor_sync(0xFFFFFFFFu, v[r], o);
    }
    if (lane == 0) {
        #pragma unroll
        for (int r = 0; r < 8; r++) wscr[wid * 8 + r] = v[r];
    }
    __syncthreads();
    if (tid < 8) {
        int s = 0;
        #pragma unroll
        for (int w = 0; w < NWARP; w++) s += wscr[w * 8 + tid];
        out8[tid] = s;
    }
    __syncthreads();
}

// warp-cooperative reverse scan over one 256-bin histogram row.
__device__ __forceinline__ int radixPick(const int* histrow, int kk, int lane,
                                         int* kknext_out) {
    int topbin = 255 - lane * 8;
    int csum = 0;
    #pragma unroll
    for (int b = 0; b < 8; b++) csum += histrow[topbin - b];
    int incl = csum;
    #pragma unroll
    for (int o = 1; o < 32; o <<= 1) {
        int t = __shfl_up_sync(0xFFFFFFFFu, incl, o);
        if (lane >= o) incl += t;
    }
    int excl = incl - csum;
    int hit = (excl < kk && kk <= incl) ? 1 : 0;
    unsigned who = __ballot_sync(0xFFFFFFFFu, hit);
    int src = __ffs(who) - 1;
    int bfound = 0, kknext = 0;
    if (hit) {
        int running = excl;
        #pragma unroll
        for (int b = 0; b < 8; b++) {
            int bin = topbin - b;
            int c = histrow[bin];
            running += c;
            if (running >= kk) { bfound = bin; kknext = kk - (running - c); break; }
        }
    }
    bfound = __shfl_sync(0xFFFFFFFFu, bfound, src);
    kknext = __shfl_sync(0xFFFFFFFFu, kknext, src);
    *kknext_out = kknext;
    return bfound;
}

// ---------------- kernel 0: tanh + quantization partials + transpose ----------
__global__ void __launch_bounds__(256) tanh_kernel(const float* __restrict__ u) {
    __shared__ float tile[32][129];
    __shared__ float scr[8];
    const int tid = threadIdx.x;
    const int i0 = blockIdx.x * 32;
    float q = 0.f;
    for (int idx = tid; idx < 32 * KDIM; idx += 256) {
        int r = idx >> 7, k = idx & 127;
        float x = tanhf(u[(i0 + r) * KDIM + k]);
        tile[r][k] = x;
        float s = (x > 0.f) ? 1.f : ((x < 0.f) ? -1.f : 0.f);
        float d = x - s;
        q += d * d;
    }
    __syncthreads();
    for (int idx = tid; idx < 32 * KDIM; idx += 256) {
        int k = idx >> 5, i = idx & 31;
        g_uhT[k * NROWS + i0 + i] = tile[i][k];
    }
    #pragma unroll
    for (int o = 16; o > 0; o >>= 1) q += __shfl_xor_sync(0xFFFFFFFFu, q, o);
    if ((tid & 31) == 0) scr[tid >> 5] = q;
    __syncthreads();
    if (tid == 0) {
        float s = 0.f;
        for (int w = 0; w < 8; w++) s += scr[w];
        g_qpart[blockIdx.x] = s;
    }
}

// ---------------- kernel 1: one-hot -> label ---------------------------------
__global__ void label_kernel(const int* __restrict__ y) {
    int i = blockIdx.x * blockDim.x + threadIdx.x;
    if (i < NROWS) {
        int lab = 0;
        const int* yr = y + (size_t)i * NCLS;
        for (int c = 0; c < NCLS; c++) {
            if (yr[c] != 0) { lab = c; break; }
        }
        g_label[i] = lab;
    }
}

// ---------------- kernel 2: GEMM inner = uh @ uh^T  --------------------------
// 64i x 512j tile, 512 threads, 8i x 8j per thread.
// B prefetched at distance 2 in registers; output stored with .cs (evict-first)
// so the 151 MB stream does not evict g_uhT from L2.
__global__ void __launch_bounds__(GTHR, 1) gemm_kernel() {
    extern __shared__ unsigned long long apk[];   // [KDIM][GTM] (a,a)-packed
    const int tid = threadIdx.x;
    const int i0 = blockIdx.x * GTM;
    const int j0 = blockIdx.y * GTN;

    for (int t = tid; t < KDIM * GTM; t += GTHR) {
        int k = t >> 6, i = t & 63;
        apk[k * GTM + i] = packww(g_uhT[(size_t)k * NROWS + i0 + i]);
    }
    __syncthreads();

    const int tjj = (tid & 63) * 8;
    const int tii = (tid >> 6) * 8;
    const float* Bp = g_uhT + (size_t)j0 + tjj;

    unsigned long long acc[8][4];
    #pragma unroll
    for (int i = 0; i < 8; i++)
        #pragma unroll
        for (int c = 0; c < 4; c++) acc[i][c] = 0ull;

    // distance-2 register prefetch, parity-rotated buffers
    ulonglong2 b01[2], b23[2];
    b01[0] = *(const ulonglong2*)(Bp);
    b23[0] = *(const ulonglong2*)(Bp + 4);
    b01[1] = *(const ulonglong2*)(Bp + (size_t)NROWS);
    b23[1] = *(const ulonglong2*)(Bp + (size_t)NROWS + 4);

    #pragma unroll 2
    for (int k = 0; k < KDIM; k++) {
        const int p = k & 1;
        ulonglong2 cb01 = b01[p], cb23 = b23[p];
        if (k + 2 < KDIM) {
            b01[p] = *(const ulonglong2*)(Bp + (size_t)(k + 2) * NROWS);
            b23[p] = *(const ulonglong2*)(Bp + (size_t)(k + 2) * NROWS + 4);
        }
        #pragma unroll
        for (int i = 0; i < 8; i++) {
            unsigned long long a = apk[k * GTM + tii + i];
            asm("fma.rn.f32x2 %0, %1, %2, %0;" : "+l"(acc[i][0]) : "l"(cb01.x), "l"(a));
            asm("fma.rn.f32x2 %0, %1, %2, %0;" : "+l"(acc[i][1]) : "l"(cb01.y), "l"(a));
            asm("fma.rn.f32x2 %0, %1, %2, %0;" : "+l"(acc[i][2]) : "l"(cb23.x), "l"(a));
            asm("fma.rn.f32x2 %0, %1, %2, %0;" : "+l"(acc[i][3]) : "l"(cb23.y), "l"(a));
        }
    }

    #pragma unroll
    for (int i = 0; i < 8; i++) {
        size_t base = (size_t)(i0 + tii + i) * NROWS + j0 + tjj;
        float4 v1, v2;
        v1.x = __uint_as_float((unsigned)(acc[i][0] & 0xFFFFFFFFull));
        v1.y = __uint_as_float((unsigned)(acc[i][0] >> 32));
        v1.z = __uint_as_float((unsigned)(acc[i][1] & 0xFFFFFFFFull));
        v1.w = __uint_as_float((unsigned)(acc[i][1] >> 32));
        v2.x = __uint_as_float((unsigned)(acc[i][2] & 0xFFFFFFFFull));
        v2.y = __uint_as_float((unsigned)(acc[i][2] >> 32));
        v2.z = __uint_as_float((unsigned)(acc[i][3] & 0xFFFFFFFFull));
        v2.w = __uint_as_float((unsigned)(acc[i][3] >> 32));
        __stcs((float4*)(g_inner + base), v1);
        __stcs((float4*)(g_inner + base + 4), v2);
    }
}

// ---------------- kernel 3: stats + loss over 8-row slabs --------------------
__global__ void __launch_bounds__(NTHR, 1) stats_loss_kernel() {
    extern __shared__ unsigned char sm[];
    float* rows          = (float*)(sm + SM_ROWS);
    unsigned char* slab  = (unsigned char*)(sm + SM_SLAB);
    unsigned char* simm  = (unsigned char*)(sm + SM_SIMM);
    int*   hist          = (int*)(sm + SM_HIST);
    float* vhist         = (float*)(sm + SM_VHIST);
    float* simv          = (float*)(sm + SM_SIMV);
    int*   scnt          = (int*)(sm + SM_SCNT);
    float* sumS8         = (float*)(sm + MISC_SUMS);
    float* sumD8         = (float*)(sm + MISC_SUMD);
    float* sgt8          = (float*)(sm + MISC_SGT);
    float* vsuf8         = (float*)(sm + MISC_VSUF);
    float* sMin8         = (float*)(sm + MISC_SMIN);
    float* BP8           = (float*)(sm + MISC_BP);
    float* BPd8          = (float*)(sm + MISC_BPD);
    float* lp8           = (float*)(sm + MISC_LP);
    float* ln8           = (float*)(sm + MISC_LN);
    int*   nsim8         = (int*)(sm + MISC_NSIM);
    int*   ksel8         = (int*)(sm + MISC_KSEL);
    int*   kk8           = (int*)(sm + MISC_KK);
    unsigned* pfx8       = (unsigned*)(sm + MISC_PFX);
    float* wscrF         = (float*)(sm + SM_WSCR);
    int*   wscrI         = (int*)(sm + SM_WSCR);

    const int tid = threadIdx.x;
    const int lane = tid & 31, wid = tid >> 5;
    const int i0  = blockIdx.x * RPB;

    // ---- setup: slab of 8 rows (streaming read), labels, zero hists ----
    {
        const float4* src = (const float4*)(g_inner + (size_t)i0 * NROWS);
        float4* dst = (float4*)rows;
        #pragma unroll 4
        for (int t = tid; t < RPB * NROWS / 4; t += NTHR) dst[t] = __ldcs(src + t);
    }
    for (int t = tid; t < NROWS; t += NTHR) slab[t] = (unsigned char)g_label[t];
    for (int t = tid; t < RPB * 256; t += NTHR) hist[t] = 0;
    if (tid < RPB) scnt[tid] = 0;
    __syncthreads();

    unsigned labr[8];
    #pragma unroll
    for (int r = 0; r < RPB; r++) labr[r] = slab[i0 + r];

    // ---- S1: sums, similarity mask, similar collection, radix pass-0 hist ----
    {
        float sS[8], sD[8];
        #pragma unroll
        for (int r = 0; r < 8; r++) { sS[r] = 0.f; sD[r] = 0.f; }
        for (int j = tid; j < NROWS; j += NTHR) {
            unsigned lab = slab[j];
            unsigned m = 0;
            #pragma unroll
            for (int r = 0; r < RPB; r++) m |= (lab == labr[r]) ? (1u << r) : 0u;
            simm[j] = (unsigned char)m;
            #pragma unroll
            for (int r = 0; r < RPB; r++) {
                float v = rows[r * NROWS + j];
                if ((m >> r) & 1u) {
                    sS[r] += v;
                    int p = atomicAdd(&scnt[r], 1);
                    if (p < SIMCAP) simv[r * SIMCAP + p] = v;
                } else {
                    sD[r] += v;
                    aggHistAdd(hist, r * 256 + (int)(f2key(v) >> 24));
                }
            }
        }
        blockSum8F(sS, wscrF, sumS8, tid);
        blockSum8F(sD, wscrF, sumD8, tid);
    }

    // ---- sMin + radix init (8-way parallel on threads 0..7) ----
    if (tid < RPB) {
        int r = tid;
        int ns = scnt[r];
        nsim8[r] = ns;
        int nd = NROWS - ns;
        int ks = nd - (nd * 9) / 10;
        if (ks < 1) ks = 1;
        ksel8[r] = ks;
        kk8[r]   = ks;
        int cnt = ns < SIMCAP ? ns : SIMCAP;
        int m = ns - (ns * 9) / 10;
        if (m < 1) m = 1;
        float* sv = simv + r * SIMCAP;
        float ssum = 0.f;
        for (int it = 0; it < m && it < cnt; it++) {
            int bi = it; float bv = sv[it];
            for (int t2 = it + 1; t2 < cnt; t2++) {
                float x = sv[t2];
                if (x < bv) { bv = x; bi = t2; }
            }
            sv[bi] = sv[it]; sv[it] = bv;
            ssum += bv;
        }
        sMin8[r] = clip64(ssum / (float)(m > 1 ? m : 1));
    }
    __syncthreads();

    // ---- radix pass-0 pick (warps 0..7) ----
    if (wid < RPB) {
        int kknext;
        int b0 = radixPick(hist + wid * 256, kk8[wid], lane, &kknext);
        if (lane == 0) { pfx8[wid] = (unsigned)b0; kk8[wid] = kknext; }
    }
    __syncthreads();

    // ---- refine sweep: byte-1 count+value hists, plus sum above byte-0 bin ---
    for (int t = tid; t < RPB * 256; t += NTHR) { hist[t] = 0; vhist[t] = 0.f; }
    __syncthreads();
    {
        unsigned p0[8];
        #pragma unroll
        for (int r = 0; r < 8; r++) p0[r] = pfx8[r];
        float sg[8];
        #pragma unroll
        for (int r = 0; r < 8; r++) sg[r] = 0.f;
        for (int j = tid; j < NROWS; j += NTHR) {
            unsigned m = simm[j];
            #pragma unroll
            for (int r = 0; r < RPB; r++) {
                if (!((m >> r) & 1u)) {
                    float v = rows[r * NROWS + j];
                    unsigned key = f2key(v);
                    unsigned hi = key >> 24;
                    if (hi > p0[r]) { sg[r] += v; }
                    else if (hi == p0[r]) {
                        int bin = (int)((key >> 16) & 255u);
                        atomicAdd(&hist[r * 256 + bin], 1);
                        atomicAdd(&vhist[r * 256 + bin], v);
                    }
                }
            }
        }
        blockSum8F(sg, wscrF, sgt8, tid);
    }
    if (wid < RPB) {
        int kknext;
        int b1 = radixPick(hist + wid * 256, kk8[wid], lane, &kknext);
        // suffix value-sum over bins > b1
        int topbin = 255 - lane * 8;
        float vp = 0.f;
        #pragma unroll
        for (int b = 0; b < 8; b++) {
            int bin = topbin - b;
            if (bin > b1) vp += vhist[wid * 256 + bin];
        }
        #pragma unroll
        for (int o = 16; o > 0; o >>= 1) vp += __shfl_xor_sync(0xFFFFFFFFu, vp, o);
        if (lane == 0) {
            // residual ties valued at the exact mean of their 16-bit bin
            float bm = vhist[wid * 256 + b1] / (float)hist[wid * 256 + b1];
            vsuf8[wid] = vp + (float)kknext * bm;
        }
    }
    __syncthreads();

    // ---- thresholds BP/BPd ----
    if (tid < RPB) {
        int r = tid;
        int ns = nsim8[r], nd = NROWS - ns;
        int ks = ksel8[r];
        float dsum = sgt8[r] + vsuf8[r];
        float dMax = clip64(dsum / (float)(ks > 1 ? ks : 1));
        float meanS  = clip64(sumS8[r] / fmaxf((float)ns, 1.f));
        float meanDS = clip64(sumD8[r] / fmaxf((float)nd, 1.f));
        float sMin = sMin8[r];
        BP8[r]  = meanS  - (64.f - meanS) / 64.f * fabsf(meanS - dMax);
        BPd8[r] = meanDS + meanDS / 64.f * fabsf(meanDS - sMin);
    }
    __syncthreads();

    // ---- S6: loss sweep ----
    {
        const float C1 = -0.2871949906334119f;  // C_COEF = -ln(99)/16
        const float C2 = 2.f * C1;              // A_COEF * C_COEF (a == 2 exactly)
        float bp[8], bpd[8];
        #pragma unroll
        for (int r = 0; r < 8; r++) { bp[r] = BP8[r]; bpd[r] = BPd8[r]; }
        float lp[8], ln_[8]; int ep[8], en[8];
        #pragma unroll
        for (int r = 0; r < 8; r++) { lp[r] = 0.f; ln_[r] = 0.f; ep[r] = 0; en[r] = 0; }
        for (int j = tid; j < NROWS; j += NTHR) {
            unsigned m = simm[j];
            #pragma unroll
            for (int r = 0; r < RPB; r++) {
                float v = rows[r * NROWS + j];
                if ((m >> r) & 1u) {
                    if (v == bp[r]) ep[r]++;
                    else {
                        float dc = v - bp[r];
                        float f = (v > bp[r]) ? C1 * dc : C2 * dc;
                        lp[r] += softplus_f(f);
                    }
                } else {
                    if (v == bpd[r]) en[r]++;
                    else {
                        float dc = v - bpd[r];
                        float f = (v < bpd[r]) ? C1 * dc : C2 * dc;
                        ln_[r] += softplus_f(-f);
                    }
                }
            }
        }
        float* ep8 = (float*)(sm + MISC_CGT);  // reuse slots (as int)
        blockSum8F(lp, wscrF, lp8, tid);
        blockSum8F(ln_, wscrF, ln8, tid);
        blockSum8I(ep, wscrI, (int*)ep8, tid);
        blockSum8I(en, wscrI, (int*)(sm + MISC_KK), tid);

        if (tid < RPB) {
            int r = tid;
            int ns = nsim8[r], nd = NROWS - ns;
            int cp = ns - ((int*)ep8)[r];
            int cn = nd - ((int*)(sm + MISC_KK))[r];
            g_rowpos[i0 + r] = lp8[r] / fmaxf((float)cp, 1.f);
            g_rowneg[i0 + r] = ln8[r] / fmaxf((float)cn, 1.f);
            g_valid[i0 + r]  = (ns > 0 && nd > 0) ? 1 : 0;
        }
    }
}

// ---------------- kernel 4: final scalar -------------------------------------
__global__ void __launch_bounds__(256) final_kernel(float* __restrict__ out) {
    __shared__ float scrF[8];
    __shared__ int scrI[8];
    int tid = threadIdx.x;
    float ps = 0.f, ns = 0.f; int cv = 0;
    for (int i = tid; i < NROWS; i += 256) {
        if (g_valid[i]) { ps += g_rowpos[i]; ns += g_rowneg[i]; cv++; }
    }
    float q = 0.f;
    for (int i = tid; i < QBLKS; i += 256) q += g_qpart[i];
    #pragma unroll
    for (int o = 16; o > 0; o >>= 1) {
        ps += __shfl_xor_sync(0xFFFFFFFFu, ps, o);
        ns += __shfl_xor_sync(0xFFFFFFFFu, ns, o);
        cv += __shfl_xor_sync(0xFFFFFFFFu, cv, o);
        q  += __shfl_xor_sync(0xFFFFFFFFu, q, o);
    }
    if ((tid & 31) == 0) { scrF[tid >> 5] = ps; scrI[tid >> 5] = cv; }
    __syncthreads();
    __shared__ float scrF2[8]; __shared__ float scrF3[8];
    if ((tid & 31) == 0) { scrF2[tid >> 5] = ns; scrF3[tid >> 5] = q; }
    __syncthreads();
    if (tid == 0) {
        float psum = 0.f, nsum = 0.f, qs = 0.f; int cnt = 0;
        for (int w = 0; w < 8; w++) {
            psum += scrF[w]; nsum += scrF2[w]; qs += scrF3[w]; cnt += scrI[w];
        }
        float posL = (cnt > 0) ? psum / fmaxf((float)cnt, 1.f) : 0.f;
        float navL = (cnt > 0) ? nsum / fmaxf((float)cnt, 1.f) : 0.f;
        float ql = 0.1f * qs / (float)(NROWS * KDIM);
        out[0] = posL + navL + ql;
    }
}

extern "C" void kernel_launch(void* const* d_in, const int* in_sizes, int n_in,
                              void* d_out, int out_size) {
    const float* u = (const float*)d_in[0];
    const int*   y = (const int*)d_in[1];
    (void)in_sizes; (void)n_in; (void)out_size;

    cudaFuncSetAttribute(gemm_kernel,
                         cudaFuncAttributeMaxDynamicSharedMemorySize, GSMEM);
    cudaFuncSetAttribute(stats_loss_kernel,
                         cudaFuncAttributeMaxDynamicSharedMemorySize, SMEM_BYTES);

    tanh_kernel<<<QBLKS, 256>>>(u);
    label_kernel<<<(NROWS + 255) / 256, 256>>>(y);
    dim3 ggrid(NROWS / GTM, NROWS / GTN);     // (96, 12)
    gemm_kernel<<<ggrid, GTHR, GSMEM>>>();
    stats_loss_kernel<<<NBLK, NTHR, SMEM_BYTES>>>();
    final_kernel<<<1, 256>>>((float*)d_out);
}